// round 1
// baseline (speedup 1.0000x reference)
#include <cuda_runtime.h>
#include <cfloat>

// Problem constants (fixed by the reference: xyz [4, 8192, 3], K=16)
#define BB   4
#define NN   8192
#define KK   16
#define QPB  128      // queries (threads) per block
#define TILE 2048     // candidates per smem tile (32 KB of float4)

__global__ __launch_bounds__(QPB)
void knn_feature_kernel(const float* __restrict__ xyz,
                        float* __restrict__ out,
                        int out_size) {
    __shared__ float4 s_tile[TILE];

    const int blocks_per_batch = NN / QPB;          // 64
    const int b  = blockIdx.x / blocks_per_batch;
    const int qb = blockIdx.x % blocks_per_batch;
    const int q  = qb * QPB + threadIdx.x;

    const float* __restrict__ base = xyz + (size_t)b * NN * 3;

    const float qx = base[3 * q + 0];
    const float qy = base[3 * q + 1];
    const float qz = base[3 * q + 2];
    const float sqi = qx * qx + qy * qy + qz * qz;

    // Top-K kept sorted DESCENDING: dist[0] is the current worst (largest).
    float dist[KK];
    int   idx[KK];
#pragma unroll
    for (int t = 0; t < KK; t++) { dist[t] = FLT_MAX; idx[t] = 0; }

    for (int t0 = 0; t0 < NN; t0 += TILE) {
        __syncthreads();
        // Cooperative tile load: float4(x, y, z, |x|^2)
        for (int j = threadIdx.x; j < TILE; j += QPB) {
            const float x = base[3 * (t0 + j) + 0];
            const float y = base[3 * (t0 + j) + 1];
            const float z = base[3 * (t0 + j) + 2];
            s_tile[j] = make_float4(x, y, z, x * x + y * y + z * z);
        }
        __syncthreads();

#pragma unroll 8
        for (int j = 0; j < TILE; j++) {
            const float4 c = s_tile[j];
            float dot = qx * c.x;
            dot = fmaf(qy, c.y, dot);
            dot = fmaf(qz, c.z, dot);
            // d2 = sqi + sqj - 2*dot ; exact 0 for the self pair
            const float d2 = fmaf(-2.0f, dot, sqi + c.w);

            if (d2 < dist[0]) {                 // strict <: ties keep lower index
                const int jj = t0 + j;
                // Parallel shift-insert: drop dist[0] (worst), place d2.
                // All compares are vs d2 against ORIGINAL dist[] -> independent.
                bool cnext = d2 < dist[1];
                bool ccur;
                dist[0] = cnext ? dist[1] : d2;
                idx[0]  = cnext ? idx[1]  : jj;
                ccur = cnext;
#pragma unroll
                for (int t = 1; t < KK - 1; t++) {
                    cnext = d2 < dist[t + 1];
                    const float dv = cnext ? dist[t + 1] : (ccur ? d2 : dist[t]);
                    const int   iv = cnext ? idx[t + 1]  : (ccur ? jj : idx[t]);
                    dist[t] = dv;
                    idx[t]  = iv;
                    ccur = cnext;
                }
                dist[KK - 1] = ccur ? d2 : dist[KK - 1];
                idx[KK - 1]  = ccur ? jj : idx[KK - 1];
            }
        }
    }

    // ---- Epilogue: features [B, N, K, 10] then indices [B, N, K] as float ----
    const size_t qlin = (size_t)b * NN + q;
    float* __restrict__ f = out + qlin * KK * 10;
    const size_t feat_total = (size_t)BB * NN * KK * 10;
    const bool write_idx = ((size_t)out_size >= feat_total + (size_t)BB * NN * KK);
    float* __restrict__ iout = out + feat_total + qlin * KK;

#pragma unroll
    for (int t = 0; t < KK; t++) {
        const int kk = KK - 1 - t;           // ascending distance order
        const int j  = idx[t];
        const float nx = base[3 * j + 0];
        const float ny = base[3 * j + 1];
        const float nz = base[3 * j + 2];
        float* p = f + kk * 10;
        p[0] = dist[t];
        p[1] = qx - nx;
        p[2] = qy - ny;
        p[3] = qz - nz;
        p[4] = qx;
        p[5] = qy;
        p[6] = qz;
        p[7] = nx;
        p[8] = ny;
        p[9] = nz;
        if (write_idx) iout[kk] = (float)j;
    }
}

extern "C" void kernel_launch(void* const* d_in, const int* in_sizes, int n_in,
                              void* d_out, int out_size) {
    const float* xyz = (const float*)d_in[0];
    float* out = (float*)d_out;
    const int grid = BB * (NN / QPB);   // 256 blocks
    knn_feature_kernel<<<grid, QPB>>>(xyz, out, out_size);
}

// round 4
// speedup vs baseline: 1.9912x; 1.9912x over previous
#include <cuda_runtime.h>
#include <cfloat>

// Problem constants (reference: xyz [4, 8192, 3], K=16)
#define BB    4
#define NN    8192
#define KK    16
#define TPB   256           // 8 warps/block
#define QPW   2             // queries per warp
#define QPB   ((TPB / 32) * QPW)   // 16 queries per block
#define TILE  2048          // candidates per smem tile (32 KB)
#define FULL  0xffffffffu

// Lexicographic "candidate strictly better than entry": (d,i) < (ed,ei)
__device__ __forceinline__ bool lex_less(float d, int i, float ed, int ei) {
    return (d < ed) || (d == ed && i < ei);
}

__global__ __launch_bounds__(TPB)
void knn_warp_kernel(const float* __restrict__ xyz,
                     float* __restrict__ out,
                     int out_size) {
    __shared__ float4 s_tile[TILE];

    const int lane = threadIdx.x & 31;
    const int wid  = threadIdx.x >> 5;
    const int seg  = lane >> 4;      // which query this lane's list entry belongs to
    const int t    = lane & 15;      // list position (ascending distance)

    const int blocks_per_batch = NN / QPB;            // 512
    const int b  = blockIdx.x / blocks_per_batch;
    const int q0 = (blockIdx.x % blocks_per_batch) * QPB + wid * QPW;

    const float* __restrict__ base = xyz + (size_t)b * NN * 3;

    // Query coords + squared norms: EXACT source expressions of the R1 passing
    // kernel (contraction decided by the compiler, not hand-written fmaf).
    const float q0x = base[3 * q0 + 0], q0y = base[3 * q0 + 1], q0z = base[3 * q0 + 2];
    const float q1x = base[3 * q0 + 3], q1y = base[3 * q0 + 4], q1z = base[3 * q0 + 5];
    const float s0 = q0x * q0x + q0y * q0y + q0z * q0z;
    const float s1 = q1x * q1x + q1y * q1y + q1z * q1z;

    // Warp-distributed sorted top-K (ascending): lane (seg, t) holds entry t of query q0+seg.
    float ld = FLT_MAX;
    int   li = 0x7fffffff;
    float tau0 = FLT_MAX, tau1 = FLT_MAX;   // current worst (entry 15) per query

    for (int tb = 0; tb < NN; tb += TILE) {
        __syncthreads();
        for (int j = threadIdx.x; j < TILE; j += TPB) {
            const float x = base[3 * (tb + j) + 0];
            const float y = base[3 * (tb + j) + 1];
            const float z = base[3 * (tb + j) + 2];
            s_tile[j] = make_float4(x, y, z, x * x + y * y + z * z);   // R1 form
        }
        __syncthreads();

        float4 c = s_tile[lane];                       // prefetch round 0
        for (int j0 = 0; j0 < TILE; j0 += 32) {
            const float4 cc = c;
            if (j0 + 32 < TILE) c = s_tile[j0 + 32 + lane];   // prefetch next round

            // Distance math: verbatim R1 expression order.
            float dot0 = q0x * cc.x;
            dot0 = fmaf(q0y, cc.y, dot0);
            dot0 = fmaf(q0z, cc.z, dot0);
            float dot1 = q1x * cc.x;
            dot1 = fmaf(q1y, cc.y, dot1);
            dot1 = fmaf(q1z, cc.z, dot1);
            const float d2a = fmaf(-2.0f, dot0, s0 + cc.w);
            const float d2b = fmaf(-2.0f, dot1, s1 + cc.w);

            unsigned m0 = __ballot_sync(FULL, d2a < tau0);
            unsigned m1 = __ballot_sync(FULL, d2b < tau1);
            if ((m0 | m1) == 0u) continue;

            // Serialize insert events in ascending lane (=index) order: exact tie-break.
            while (m0) {
                const int src = __ffs(m0) - 1;
                m0 &= m0 - 1;
                const float dv = __shfl_sync(FULL, d2a, src);
                const int   iv = tb + j0 + src;
                const float pd = __shfl_up_sync(FULL, ld, 1, 16);
                const int   pi = __shfl_up_sync(FULL, li, 1, 16);
                const bool ct = lex_less(dv, iv, ld, li);
                const bool cp = (t > 0) && lex_less(dv, iv, pd, pi);
                if (seg == 0 && ct) {
                    ld = cp ? pd : dv;
                    li = cp ? pi : iv;
                }
            }
            while (m1) {
                const int src = __ffs(m1) - 1;
                m1 &= m1 - 1;
                const float dv = __shfl_sync(FULL, d2b, src);
                const int   iv = tb + j0 + src;
                const float pd = __shfl_up_sync(FULL, ld, 1, 16);
                const int   pi = __shfl_up_sync(FULL, li, 1, 16);
                const bool ct = lex_less(dv, iv, ld, li);
                const bool cp = (t > 0) && lex_less(dv, iv, pd, pi);
                if (seg == 1 && ct) {
                    ld = cp ? pd : dv;
                    li = cp ? pi : iv;
                }
            }
            // Refresh thresholds (entry 15 of each segment).
            tau0 = __shfl_sync(FULL, ld, 15);
            tau1 = __shfl_sync(FULL, ld, 31);
        }
    }

    // ---- Epilogue: features [B, N, K, 10] then indices [B, N, K] as float ----
    const int   q  = q0 + seg;
    const float qx = seg ? q1x : q0x;
    const float qy = seg ? q1y : q0y;
    const float qz = seg ? q1z : q0z;

    const size_t qlin = (size_t)b * NN + q;
    const size_t feat_total = (size_t)BB * NN * KK * 10;
    const bool write_idx = ((size_t)out_size >= feat_total + (size_t)BB * NN * KK);

    const int j = li;
    const float nx = base[3 * j + 0];
    const float ny = base[3 * j + 1];
    const float nz = base[3 * j + 2];

    float* p = out + qlin * KK * 10 + (size_t)t * 10;
    p[0] = ld;
    p[1] = qx - nx;
    p[2] = qy - ny;
    p[3] = qz - nz;
    p[4] = qx;
    p[5] = qy;
    p[6] = qz;
    p[7] = nx;
    p[8] = ny;
    p[9] = nz;
    if (write_idx) out[feat_total + qlin * KK + t] = (float)j;
}

extern "C" void kernel_launch(void* const* d_in, const int* in_sizes, int n_in,
                              void* d_out, int out_size) {
    const float* xyz = (const float*)d_in[0];
    float* out = (float*)d_out;
    const int grid = BB * (NN / QPB);   // 2048 blocks
    knn_warp_kernel<<<grid, TPB>>>(xyz, out, out_size);
}

// round 5
// speedup vs baseline: 2.4043x; 1.2075x over previous
#include <cuda_runtime.h>
#include <cfloat>

// Problem constants (reference: xyz [4, 8192, 3], K=16)
#define BB    4
#define NN    8192
#define KK    16
#define TPB   256           // 8 warps/block
#define QPW   2             // queries per warp
#define QPB   ((TPB / 32) * QPW)   // 16 queries per block
#define TILE  1024          // candidates per smem tile (16 KB -> 8 blocks/SM)
#define FULL  0xffffffffu

// Lexicographic "candidate strictly better than entry": (d,i) < (ed,ei)
__device__ __forceinline__ bool lex_less(float d, int i, float ed, int ei) {
    return (d < ed) || (d == ed && i < ei);
}

// Ascending lexicographic bitonic sort of 32 (d,i) pairs across the warp.
// Equivalent to inserting all 32 into an empty lex-ordered list.
__device__ __forceinline__ void bitonic32(float& d, int& i, int lane) {
#pragma unroll
    for (int k = 2; k <= 32; k <<= 1) {
#pragma unroll
        for (int j = k >> 1; j > 0; j >>= 1) {
            const float od = __shfl_xor_sync(FULL, d, j);
            const int   oi = __shfl_xor_sync(FULL, i, j);
            const bool keep_min = ((lane & k) == 0) == ((lane & j) == 0);
            const bool less = lex_less(od, oi, d, i);   // other < mine
            if (keep_min == less) { d = od; i = oi; }
        }
    }
}

__global__ __launch_bounds__(TPB)
void knn_warp_kernel(const float* __restrict__ xyz,
                     float* __restrict__ out,
                     int out_size) {
    __shared__ float4 s_tile[TILE];

    const int lane = threadIdx.x & 31;
    const int wid  = threadIdx.x >> 5;
    const int seg  = lane >> 4;      // which query this lane's list entry belongs to
    const int t    = lane & 15;      // list position (ascending distance)

    const int blocks_per_batch = NN / QPB;            // 512
    const int b  = blockIdx.x / blocks_per_batch;
    const int q0 = (blockIdx.x % blocks_per_batch) * QPB + wid * QPW;

    const float* __restrict__ base = xyz + (size_t)b * NN * 3;

    // Query coords + squared norms: EXACT R1 source expressions (frozen).
    const float q0x = base[3 * q0 + 0], q0y = base[3 * q0 + 1], q0z = base[3 * q0 + 2];
    const float q1x = base[3 * q0 + 3], q1y = base[3 * q0 + 4], q1z = base[3 * q0 + 5];
    const float s0 = q0x * q0x + q0y * q0y + q0z * q0z;
    const float s1 = q1x * q1x + q1y * q1y + q1z * q1z;

    // Warp-distributed sorted top-K (ascending): lane (seg, t) holds entry t of query q0+seg.
    float ld = FLT_MAX;
    int   li = 0x7fffffff;
    float tau0 = FLT_MAX, tau1 = FLT_MAX;

    for (int tb = 0; tb < NN; tb += TILE) {
        __syncthreads();
        for (int j = threadIdx.x; j < TILE; j += TPB) {
            const float x = base[3 * (tb + j) + 0];
            const float y = base[3 * (tb + j) + 1];
            const float z = base[3 * (tb + j) + 2];
            s_tile[j] = make_float4(x, y, z, x * x + y * y + z * z);   // R1 form
        }
        __syncthreads();

        int j0 = 0;
        if (tb == 0) {
            // ---- Warmup: bootstrap both 16-lists from candidates 0..31 via
            // two lex bitonic sorts instead of 64 serialized insert events. ----
            const float4 cw = s_tile[lane];
            float dot0 = q0x * cw.x;
            dot0 = fmaf(q0y, cw.y, dot0);
            dot0 = fmaf(q0z, cw.z, dot0);
            float dot1 = q1x * cw.x;
            dot1 = fmaf(q1y, cw.y, dot1);
            dot1 = fmaf(q1z, cw.z, dot1);
            const float d2a = fmaf(-2.0f, dot0, s0 + cw.w);
            const float d2b = fmaf(-2.0f, dot1, s1 + cw.w);

            float da = d2a; int ia = lane;
            bitonic32(da, ia, lane);
            float db = d2b; int ib = lane;
            bitonic32(db, ib, lane);
            // seg0 lanes keep query0 ranks 0..15 (= their lane); seg1 lanes
            // fetch query1 rank t from lane t of the second sort.
            const float d1 = __shfl_sync(FULL, db, (lane - 16) & 31);
            const int   i1 = __shfl_sync(FULL, ib, (lane - 16) & 31);
            ld = seg ? d1 : da;
            li = seg ? i1 : ia;
            tau0 = __shfl_sync(FULL, ld, 15);
            tau1 = __shfl_sync(FULL, ld, 31);
            j0 = 32;
        }

        float4 c = s_tile[j0 + lane];                  // prefetch first round
        for (; j0 < TILE; j0 += 32) {
            const float4 cc = c;
            if (j0 + 32 < TILE) c = s_tile[j0 + 32 + lane];   // prefetch next round

            // Distance math: verbatim R1 expression order (frozen).
            float dot0 = q0x * cc.x;
            dot0 = fmaf(q0y, cc.y, dot0);
            dot0 = fmaf(q0z, cc.z, dot0);
            float dot1 = q1x * cc.x;
            dot1 = fmaf(q1y, cc.y, dot1);
            dot1 = fmaf(q1z, cc.z, dot1);
            const float d2a = fmaf(-2.0f, dot0, s0 + cc.w);
            const float d2b = fmaf(-2.0f, dot1, s1 + cc.w);

            unsigned m0 = __ballot_sync(FULL, d2a < tau0);
            unsigned m1 = __ballot_sync(FULL, d2b < tau1);
            if ((m0 | m1) == 0u) continue;

            // Serialize insert events in ascending lane (=index) order.
            while (m0) {
                const int src = __ffs(m0) - 1;
                m0 &= m0 - 1;
                const float dv = __shfl_sync(FULL, d2a, src);
                const int   iv = tb + j0 + src;
                const float pd = __shfl_up_sync(FULL, ld, 1, 16);
                const int   pi = __shfl_up_sync(FULL, li, 1, 16);
                const bool ct = lex_less(dv, iv, ld, li);
                const bool cp = (t > 0) && lex_less(dv, iv, pd, pi);
                if (seg == 0 && ct) {
                    ld = cp ? pd : dv;
                    li = cp ? pi : iv;
                }
            }
            while (m1) {
                const int src = __ffs(m1) - 1;
                m1 &= m1 - 1;
                const float dv = __shfl_sync(FULL, d2b, src);
                const int   iv = tb + j0 + src;
                const float pd = __shfl_up_sync(FULL, ld, 1, 16);
                const int   pi = __shfl_up_sync(FULL, li, 1, 16);
                const bool ct = lex_less(dv, iv, ld, li);
                const bool cp = (t > 0) && lex_less(dv, iv, pd, pi);
                if (seg == 1 && ct) {
                    ld = cp ? pd : dv;
                    li = cp ? pi : iv;
                }
            }
            tau0 = __shfl_sync(FULL, ld, 15);
            tau1 = __shfl_sync(FULL, ld, 31);
        }
    }

    // ---- Epilogue: features [B, N, K, 10] then indices [B, N, K] as float ----
    const int   q  = q0 + seg;
    const float qx = seg ? q1x : q0x;
    const float qy = seg ? q1y : q0y;
    const float qz = seg ? q1z : q0z;

    const size_t qlin = (size_t)b * NN + q;
    const size_t feat_total = (size_t)BB * NN * KK * 10;
    const bool write_idx = ((size_t)out_size >= feat_total + (size_t)BB * NN * KK);

    const int j = li;
    const float nx = base[3 * j + 0];
    const float ny = base[3 * j + 1];
    const float nz = base[3 * j + 2];

    float* p = out + qlin * KK * 10 + (size_t)t * 10;
    p[0] = ld;
    p[1] = qx - nx;
    p[2] = qy - ny;
    p[3] = qz - nz;
    p[4] = qx;
    p[5] = qy;
    p[6] = qz;
    p[7] = nx;
    p[8] = ny;
    p[9] = nz;
    if (write_idx) out[feat_total + qlin * KK + t] = (float)j;
}

extern "C" void kernel_launch(void* const* d_in, const int* in_sizes, int n_in,
                              void* d_out, int out_size) {
    const float* xyz = (const float*)d_in[0];
    float* out = (float*)d_out;
    const int grid = BB * (NN / QPB);   // 2048 blocks
    knn_warp_kernel<<<grid, TPB>>>(xyz, out, out_size);
}

// round 6
// speedup vs baseline: 2.5278x; 1.0514x over previous
#include <cuda_runtime.h>
#include <cfloat>

// Problem constants (reference: xyz [4, 8192, 3], K=16)
#define BB    4
#define NN    8192
#define KK    16
#define TPB   256           // 8 warps/block
#define QPW   2             // queries per warp
#define QPB   ((TPB / 32) * QPW)   // 16 queries per block
#define TILE  1024          // candidates per smem tile
#define PAD   32            // prefetch overrun pad
#define FULL  0xffffffffu

// Lexicographic "candidate strictly better than entry": (d,i) < (ed,ei)
__device__ __forceinline__ bool lex_less(float d, int i, float ed, int ei) {
    return (d < ed) || (d == ed && i < ei);
}

// Ascending lexicographic bitonic sort of 32 (d,i) pairs across the warp.
__device__ __forceinline__ void bitonic32(float& d, int& i, int lane) {
#pragma unroll
    for (int k = 2; k <= 32; k <<= 1) {
#pragma unroll
        for (int j = k >> 1; j > 0; j >>= 1) {
            const float od = __shfl_xor_sync(FULL, d, j);
            const int   oi = __shfl_xor_sync(FULL, i, j);
            const bool keep_min = ((lane & k) == 0) == ((lane & j) == 0);
            const bool less = lex_less(od, oi, d, i);   // other < mine
            if (keep_min == less) { d = od; i = oi; }
        }
    }
}

__global__ __launch_bounds__(TPB)
void knn_warp_kernel(const float* __restrict__ xyz,
                     float* __restrict__ out,
                     int out_size) {
    __shared__ float4 s_tile[TILE + PAD];

    const int lane = threadIdx.x & 31;
    const int wid  = threadIdx.x >> 5;
    const int seg  = lane >> 4;      // which query this lane's list entry belongs to
    const int t    = lane & 15;      // list position (ascending distance)

    const int blocks_per_batch = NN / QPB;            // 512
    const int b  = blockIdx.x / blocks_per_batch;
    const int q0 = (blockIdx.x % blocks_per_batch) * QPB + wid * QPW;

    const float* __restrict__ base = xyz + (size_t)b * NN * 3;

    // Query coords + squared norms: EXACT R1 source expressions (frozen).
    const float q0x = base[3 * q0 + 0], q0y = base[3 * q0 + 1], q0z = base[3 * q0 + 2];
    const float q1x = base[3 * q0 + 3], q1y = base[3 * q0 + 4], q1z = base[3 * q0 + 5];
    const float s0 = q0x * q0x + q0y * q0y + q0z * q0z;
    const float s1 = q1x * q1x + q1y * q1y + q1z * q1z;

    // Warp-distributed sorted top-K: lane (seg, t) holds entry t of query q0+seg.
    float ld = FLT_MAX;
    int   li = 0x7fffffff;
    float tau0 = FLT_MAX, tau1 = FLT_MAX;

    // One candidate round: distances (frozen R1 arithmetic), ballot, insert events.
#define ROUND(CC, JBASE)                                                        \
    {                                                                           \
        float dot0 = q0x * (CC).x;                                              \
        dot0 = fmaf(q0y, (CC).y, dot0);                                         \
        dot0 = fmaf(q0z, (CC).z, dot0);                                         \
        float dot1 = q1x * (CC).x;                                              \
        dot1 = fmaf(q1y, (CC).y, dot1);                                         \
        dot1 = fmaf(q1z, (CC).z, dot1);                                         \
        const float d2a = fmaf(-2.0f, dot0, s0 + (CC).w);                       \
        const float d2b = fmaf(-2.0f, dot1, s1 + (CC).w);                       \
        unsigned m0 = __ballot_sync(FULL, d2a < tau0);                          \
        unsigned m1 = __ballot_sync(FULL, d2b < tau1);                          \
        if (m0 | m1) {                                                          \
            const bool had0 = (m0 != 0), had1 = (m1 != 0);                      \
            while (m0) {                                                        \
                const int src = __ffs(m0) - 1;                                  \
                m0 &= m0 - 1;                                                   \
                const float dv = __shfl_sync(FULL, d2a, src);                   \
                const int   iv = (JBASE) + src;                                 \
                const float pd = __shfl_up_sync(FULL, ld, 1, 16);               \
                const int   pi = __shfl_up_sync(FULL, li, 1, 16);               \
                const bool ct = lex_less(dv, iv, ld, li);                       \
                const bool cp = (t > 0) && lex_less(dv, iv, pd, pi);            \
                if (seg == 0 && ct) { ld = cp ? pd : dv; li = cp ? pi : iv; }   \
            }                                                                   \
            while (m1) {                                                        \
                const int src = __ffs(m1) - 1;                                  \
                m1 &= m1 - 1;                                                   \
                const float dv = __shfl_sync(FULL, d2b, src);                   \
                const int   iv = (JBASE) + src;                                 \
                const float pd = __shfl_up_sync(FULL, ld, 1, 16);               \
                const int   pi = __shfl_up_sync(FULL, li, 1, 16);               \
                const bool ct = lex_less(dv, iv, ld, li);                       \
                const bool cp = (t > 0) && lex_less(dv, iv, pd, pi);            \
                if (seg == 1 && ct) { ld = cp ? pd : dv; li = cp ? pi : iv; }   \
            }                                                                   \
            if (had0) tau0 = __shfl_sync(FULL, ld, 15);                         \
            if (had1) tau1 = __shfl_sync(FULL, ld, 31);                         \
        }                                                                       \
    }

    for (int tb = 0; tb < NN; tb += TILE) {
        __syncthreads();
        for (int j = threadIdx.x; j < TILE; j += TPB) {
            const float x = base[3 * (tb + j) + 0];
            const float y = base[3 * (tb + j) + 1];
            const float z = base[3 * (tb + j) + 2];
            s_tile[j] = make_float4(x, y, z, x * x + y * y + z * z);   // R1 form
        }
        __syncthreads();

        int j0 = 0;
        if (tb == 0) {
            // Warmup: bootstrap both lists from candidates 0..31 via lex bitonic sorts.
            const float4 cw = s_tile[lane];
            float dot0 = q0x * cw.x;
            dot0 = fmaf(q0y, cw.y, dot0);
            dot0 = fmaf(q0z, cw.z, dot0);
            float dot1 = q1x * cw.x;
            dot1 = fmaf(q1y, cw.y, dot1);
            dot1 = fmaf(q1z, cw.z, dot1);
            const float d2a = fmaf(-2.0f, dot0, s0 + cw.w);
            const float d2b = fmaf(-2.0f, dot1, s1 + cw.w);

            float da = d2a; int ia = lane;
            bitonic32(da, ia, lane);
            float db = d2b; int ib = lane;
            bitonic32(db, ib, lane);
            const float d1 = __shfl_sync(FULL, db, (lane - 16) & 31);
            const int   i1 = __shfl_sync(FULL, ib, (lane - 16) & 31);
            ld = seg ? d1 : da;
            li = seg ? i1 : ia;
            tau0 = __shfl_sync(FULL, ld, 15);
            tau1 = __shfl_sync(FULL, ld, 31);
            j0 = 32;
        }

        // Double-pumped candidate loop with unconditional (padded) prefetch.
        float4 c = s_tile[j0 + lane];
        for (; j0 + 64 <= TILE; j0 += 64) {
            const float4 cA = c;
            float4 cB = s_tile[j0 + 32 + lane];
            ROUND(cA, tb + j0);
            c = s_tile[j0 + 64 + lane];          // pad absorbs last-iter overrun
            ROUND(cB, tb + j0 + 32);
        }
        if (j0 < TILE) {                          // tail round (warmup tiles only)
            ROUND(c, tb + j0);
        }
    }
#undef ROUND

    // ---- Epilogue: features [B, N, K, 10] then indices [B, N, K] as float ----
    const int   q  = q0 + seg;
    const float qx = seg ? q1x : q0x;
    const float qy = seg ? q1y : q0y;
    const float qz = seg ? q1z : q0z;

    const size_t qlin = (size_t)b * NN + q;
    const size_t feat_total = (size_t)BB * NN * KK * 10;
    const bool write_idx = ((size_t)out_size >= feat_total + (size_t)BB * NN * KK);

    const int j = li;
    const float nx = base[3 * j + 0];
    const float ny = base[3 * j + 1];
    const float nz = base[3 * j + 2];

    float* p = out + qlin * KK * 10 + (size_t)t * 10;
    p[0] = ld;
    p[1] = qx - nx;
    p[2] = qy - ny;
    p[3] = qz - nz;
    p[4] = qx;
    p[5] = qy;
    p[6] = qz;
    p[7] = nx;
    p[8] = ny;
    p[9] = nz;
    if (write_idx) out[feat_total + qlin * KK + t] = (float)j;
}

extern "C" void kernel_launch(void* const* d_in, const int* in_sizes, int n_in,
                              void* d_out, int out_size) {
    const float* xyz = (const float*)d_in[0];
    float* out = (float*)d_out;
    const int grid = BB * (NN / QPB);   // 2048 blocks
    knn_warp_kernel<<<grid, TPB>>>(xyz, out, out_size);
}